// round 1
// baseline (speedup 1.0000x reference)
#include <cuda_runtime.h>
#include <cstddef>

// Problem constants
#define BB   2048
#define TT   512
#define D_IN 4
#define HH   64
#define LL   4
#define OUTN 5
#define G4   256   // 4*H

// Scratch (device globals are the sanctioned allocation-free workaround)
__device__ float g_hsA[(size_t)TT * BB * HH];   // 256 MB
__device__ float g_hsB[(size_t)TT * BB * HH];   // 256 MB
__device__ float g_W[LL][G4 * 128];             // combined [Wih|Whh], row stride 128
__device__ float g_bias[LL][G4];                // b_ih + b_hh

// ---------------------------------------------------------------------------
// Weight prep: build combined gate weights + bias per layer.
// ---------------------------------------------------------------------------
__global__ void prep_kernel(const float* __restrict__ W_ih0,
                            const float* __restrict__ W_ihr,
                            const float* __restrict__ W_hh,
                            const float* __restrict__ b_ih,
                            const float* __restrict__ b_hh) {
    int g = blockIdx.x * blockDim.x + threadIdx.x;   // 0..1023
    if (g >= LL * G4) return;
    int l = g >> 8, gate = g & 255;
    float* dst = &g_W[l][gate * 128];
    if (l == 0) {
        #pragma unroll
        for (int k = 0; k < D_IN; k++) dst[k] = W_ih0[gate * D_IN + k];
        for (int k = 0; k < HH; k++)   dst[D_IN + k] = W_hh[gate * HH + k]; // W_hh[0]
    } else {
        for (int k = 0; k < HH; k++) dst[k]      = W_ihr[((size_t)(l - 1) * G4 + gate) * HH + k];
        for (int k = 0; k < HH; k++) dst[HH + k] = W_hh[((size_t)l * G4 + gate) * HH + k];
    }
    g_bias[l][gate] = b_ih[l * G4 + gate] + b_hh[l * G4 + gate];
}

// ---------------------------------------------------------------------------
// Gate nonlinearities (MUFU EX2 based, ~1e-6 rel error, saturates correctly)
// ---------------------------------------------------------------------------
__device__ __forceinline__ float sigf(float x) {
    return __fdividef(1.0f, 1.0f + __expf(-x));
}
__device__ __forceinline__ float tanhg(float x) {
    return __fdividef(2.0f, 1.0f + __expf(-2.0f * x)) - 1.0f;
}

// ---------------------------------------------------------------------------
// Persistent per-layer LSTM kernel.
//   KIN = 4 (layer 0, input x [B,T,4]) or 64 (layers 1-3, input hs [T,B,H]).
//   Grid: 128 CTAs x 256 threads; CTA owns 16 batch rows for all T steps.
//   Thread (u = tid&63, rq = tid>>6) owns unit u of rows {rq, rq+4, rq+8, rq+12}.
//   Warp lanes share rq -> A loads broadcast; u contiguous + odd word stride
//   -> conflict-free W loads.
// ---------------------------------------------------------------------------
template <int KIN>
__global__ void __launch_bounds__(256, 1)
lstm_layer(const float* __restrict__ in, int layer, float* __restrict__ ouths) {
    constexpr int K    = KIN + HH;
    constexpr int APAD = (((K / 4) & 1) == 0) ? (K + 4) : K;  // odd 16B-word stride
    constexpr int AW   = APAD / 4;

    extern __shared__ float smem[];
    float* Ws = smem;                 // G4 * APAD
    float* As = smem + G4 * APAD;     // 16 * APAD  ([x_t | h] per row)

    const int tid     = threadIdx.x;
    const int u       = tid & 63;
    const int rq      = tid >> 6;
    const int rowbase = blockIdx.x * 16;

    // Load padded weights into SMEM (one-time)
    const float* Wg = g_W[layer];
    for (int idx = tid; idx < G4 * K; idx += 256) {
        int g = idx / K, k = idx - g * K;
        Ws[g * APAD + k] = Wg[g * 128 + k];
    }
    // Zero A (h part must start at 0)
    for (int idx = tid; idx < 16 * APAD; idx += 256) As[idx] = 0.0f;
    __syncthreads();

    const float bi = g_bias[layer][u];
    const float bf = g_bias[layer][64 + u];
    const float bg = g_bias[layer][128 + u];
    const float bo = g_bias[layer][192 + u];

    float c[4] = {0.f, 0.f, 0.f, 0.f};

    const float4* As4 = (const float4*)As;
    const float4* Ws4 = (const float4*)Ws;

    for (int t = 0; t < TT; ++t) {
        // Stage x_t into As[:, 0:KIN)
        if (KIN == 4) {
            if (tid < 64) {
                int r = tid >> 2, i = tid & 3;
                As[r * APAD + i] =
                    in[(size_t)(rowbase + r) * (TT * D_IN) + t * D_IN + i];
            }
        } else {
            int r  = tid >> 4;          // 0..15
            int kk = (tid & 15) * 4;    // 0..60
            float4 v = *(const float4*)&in[(size_t)t * (BB * HH) +
                                           (size_t)(rowbase + r) * HH + kk];
            *(float4*)&As[r * APAD + kk] = v;
        }
        __syncthreads();

        // GEMM: acc[q][rr] = sum_k A[row][k] * W[q*64+u][k]
        float acc[4][4];
        #pragma unroll
        for (int q = 0; q < 4; q++)
            #pragma unroll
            for (int rr = 0; rr < 4; rr++) acc[q][rr] = 0.0f;

        #pragma unroll 4
        for (int k4 = 0; k4 < K / 4; ++k4) {
            float4 a[4];
            #pragma unroll
            for (int rr = 0; rr < 4; rr++)
                a[rr] = As4[(rq + 4 * rr) * AW + k4];
            #pragma unroll
            for (int q = 0; q < 4; q++) {
                float4 w = Ws4[(q * 64 + u) * AW + k4];
                #pragma unroll
                for (int rr = 0; rr < 4; rr++) {
                    acc[q][rr] = fmaf(w.x, a[rr].x, acc[q][rr]);
                    acc[q][rr] = fmaf(w.y, a[rr].y, acc[q][rr]);
                    acc[q][rr] = fmaf(w.z, a[rr].z, acc[q][rr]);
                    acc[q][rr] = fmaf(w.w, a[rr].w, acc[q][rr]);
                }
            }
        }
        __syncthreads();  // everyone done reading As before we overwrite h

        // LSTM epilogue (thread-local: all 4 gates of unit u, rows rq+4*rr)
        #pragma unroll
        for (int rr = 0; rr < 4; rr++) {
            int row  = rq + 4 * rr;
            float gi = sigf(acc[0][rr] + bi);
            float gf = sigf(acc[1][rr] + bf);
            float gg = tanhg(acc[2][rr] + bg);
            float go = sigf(acc[3][rr] + bo);
            float cn = gf * c[rr] + gi * gg;
            c[rr]    = cn;
            float hn = go * tanhg(cn);
            As[row * APAD + KIN + u] = hn;  // feed back for next step
            ouths[(size_t)t * (BB * HH) + (size_t)(rowbase + row) * HH + u] = hn;
        }
        // next iteration's top-of-loop __syncthreads publishes h writes
    }
}

// ---------------------------------------------------------------------------
// Final FC on last timestep of top layer: out[b][o] = h . W_fc[o] + b_fc[o]
// ---------------------------------------------------------------------------
__global__ void fc_kernel(const float* __restrict__ hs,
                          const float* __restrict__ Wfc,
                          const float* __restrict__ bfc,
                          float* __restrict__ out) {
    int idx = blockIdx.x * blockDim.x + threadIdx.x;
    if (idx >= BB * OUTN) return;
    int b = idx / OUTN, o = idx - b * OUTN;
    const float* h = &hs[(size_t)(TT - 1) * (BB * HH) + (size_t)b * HH];
    float s = bfc[o];
    #pragma unroll
    for (int j = 0; j < HH; j++) s = fmaf(h[j], Wfc[o * HH + j], s);
    out[idx] = s;
}

// ---------------------------------------------------------------------------
extern "C" void kernel_launch(void* const* d_in, const int* in_sizes, int n_in,
                              void* d_out, int out_size) {
    const float* x     = (const float*)d_in[0];
    const float* W_ih0 = (const float*)d_in[1];
    const float* W_ihr = (const float*)d_in[2];
    const float* W_hh  = (const float*)d_in[3];
    const float* b_ih  = (const float*)d_in[4];
    const float* b_hh  = (const float*)d_in[5];
    const float* W_fc  = (const float*)d_in[6];
    const float* b_fc  = (const float*)d_in[7];
    float* out = (float*)d_out;

    float *hsA = nullptr, *hsB = nullptr;
    cudaGetSymbolAddress((void**)&hsA, g_hsA);
    cudaGetSymbolAddress((void**)&hsB, g_hsB);

    // Dynamic SMEM sizes: (256 + 16) rows * APAD floats
    constexpr int SMEM_L0 = (G4 + 16) * 68  * 4;   //  73,984 B (K=68, APAD=68)
    constexpr int SMEM_LN = (G4 + 16) * 132 * 4;   // 143,616 B (K=128, APAD=132)
    cudaFuncSetAttribute(lstm_layer<4>,
                         cudaFuncAttributeMaxDynamicSharedMemorySize, SMEM_L0);
    cudaFuncSetAttribute(lstm_layer<64>,
                         cudaFuncAttributeMaxDynamicSharedMemorySize, SMEM_LN);

    prep_kernel<<<4, 256>>>(W_ih0, W_ihr, W_hh, b_ih, b_hh);

    lstm_layer<4><<<BB / 16, 256, SMEM_L0>>>(x,   0, hsA);
    lstm_layer<64><<<BB / 16, 256, SMEM_LN>>>(hsA, 1, hsB);
    lstm_layer<64><<<BB / 16, 256, SMEM_LN>>>(hsB, 2, hsA);
    lstm_layer<64><<<BB / 16, 256, SMEM_LN>>>(hsA, 3, hsB);

    fc_kernel<<<(BB * OUTN + 255) / 256, 256>>>(hsB, W_fc, b_fc, out);
}